// round 8
// baseline (speedup 1.0000x reference)
#include <cuda_runtime.h>
#include <cuda_bf16.h>

// Problem constants
#define SQ   1024   // sequence length
#define BB   8      // batch
#define HH   1024   // hidden
#define NHD  16     // num heads
#define HDI  64     // head dim

// ---------------------------------------------------------------------------
// Scratch (device globals: no allocation allowed)
// ---------------------------------------------------------------------------
__device__ float g_qp[(size_t)BB * NHD * SQ * HDI];   // [b][h][s][d]
__device__ float g_kp[(size_t)BB * NHD * SQ * HDI];
__device__ float g_vp[(size_t)BB * NHD * SQ * HDI];
__device__ float g_bias[BB * SQ];                     // -1e6 * mask
__device__ float g_psum[(size_t)BB * NHD * SQ * 8];   // partial row sums (per k-block)
__device__ float g_rinv[(size_t)BB * NHD * SQ];       // 1 / rowsum
__device__ int   g_mmode;

// ---------------------------------------------------------------------------
// TF32 helpers
// ---------------------------------------------------------------------------
__device__ __forceinline__ unsigned f2tf(float x) {
    unsigned u;
    asm("cvt.rna.tf32.f32 %0, %1;" : "=r"(u) : "f"(x));
    return u;
}
__device__ __forceinline__ uint4 f2tf4(float4 v) {
    return make_uint4(f2tf(v.x), f2tf(v.y), f2tf(v.z), f2tf(v.w));
}
__device__ __forceinline__ void mma8(float c[4], const unsigned a[4], const unsigned b[2]) {
    asm volatile(
        "mma.sync.aligned.m16n8k8.row.col.f32.tf32.tf32.f32 "
        "{%0,%1,%2,%3}, {%4,%5,%6,%7}, {%8,%9}, {%0,%1,%2,%3};"
        : "+f"(c[0]), "+f"(c[1]), "+f"(c[2]), "+f"(c[3])
        : "r"(a[0]), "r"(a[1]), "r"(a[2]), "r"(a[3]),
          "r"(b[0]), "r"(b[1]));
}

// ---------------------------------------------------------------------------
// Mask dtype detection + bias build
// ---------------------------------------------------------------------------
__global__ void k_detect(const unsigned* __restrict__ m) {
    bool i32 = true, f32 = true;
    for (int i = 0; i < 2048; i++) {
        unsigned v = m[i];
        if (v > 1u) i32 = false;
        if (v != 0u && v != 0x3F800000u) f32 = false;
    }
    g_mmode = i32 ? 1 : (f32 ? 2 : 0);
}
__global__ void k_bias(const void* __restrict__ mask) {
    int i = blockIdx.x * blockDim.x + threadIdx.x;
    if (i >= BB * SQ) return;
    int mode = g_mmode;
    float v;
    if (mode == 1)      v = (float)((const int*)mask)[i];
    else if (mode == 2) v = ((const float*)mask)[i];
    else                v = (float)((const unsigned char*)mask)[i];
    g_bias[i] = v * -1000000.0f;
}

// ---------------------------------------------------------------------------
// Projection GEMM (all 3 in one launch, blockIdx.z selects which):
//   Out[b][h][s][d] = X[m=s*B+b] . W[n] + bias[n]
// BM=128, BN=128, BK=32, 256 thr = 8 warps (2 x 4), warp tile 64x32.
// TF32 pre-converted in smem; pad stride 36 (36%32==4 -> conflict-free frags).
// ---------------------------------------------------------------------------
__global__ __launch_bounds__(256) void k_proj(
    const float* __restrict__ Xq, const float* __restrict__ Xk, const float* __restrict__ Xv,
    const float* __restrict__ Wq, const float* __restrict__ bq,
    const float* __restrict__ Wk, const float* __restrict__ bk,
    const float* __restrict__ Wv, const float* __restrict__ bv)
{
    const int which = blockIdx.z;
    const float* X    = (which == 0) ? Xq : ((which == 1) ? Xk : Xv);
    const float* W    = (which == 0) ? Wq : ((which == 1) ? Wk : Wv);
    const float* bias = (which == 0) ? bq : ((which == 1) ? bk : bv);
    float* Out        = (which == 0) ? g_qp : ((which == 1) ? g_kp : g_vp);

    __shared__ unsigned As[128][36];
    __shared__ unsigned Bs[128][36];

    const int tid  = threadIdx.x;
    const int lane = tid & 31;
    const int warp = tid >> 5;
    const int wm   = warp >> 2;     // 0..1
    const int wn   = warp & 3;      // 0..3
    const int g    = lane >> 2;
    const int t4   = lane & 3;
    const int bm   = blockIdx.y * 128;
    const int bn   = blockIdx.x * 128;

    float acc[4][4][4];
#pragma unroll
    for (int mt = 0; mt < 4; mt++)
#pragma unroll
        for (int nt = 0; nt < 4; nt++)
#pragma unroll
            for (int i = 0; i < 4; i++) acc[mt][nt][i] = 0.0f;

    for (int k0 = 0; k0 < HH; k0 += 32) {
#pragma unroll
        for (int t = 0; t < 4; t++) {
            int i4 = tid + t * 256;
            int r  = i4 >> 3;
            int c  = (i4 & 7) << 2;
            float4 a4 = *reinterpret_cast<const float4*>(&X[(size_t)(bm + r) * HH + k0 + c]);
            *reinterpret_cast<uint4*>(&As[r][c]) = f2tf4(a4);
            float4 b4 = *reinterpret_cast<const float4*>(&W[(size_t)(bn + r) * HH + k0 + c]);
            *reinterpret_cast<uint4*>(&Bs[r][c]) = f2tf4(b4);
        }
        __syncthreads();

#pragma unroll
        for (int k8 = 0; k8 < 4; k8++) {
            const int kk = k8 * 8;
            unsigned a[4][4], bf[4][2];
#pragma unroll
            for (int mt = 0; mt < 4; mt++) {
                const int r = wm * 64 + mt * 16;
                a[mt][0] = As[r + g][kk + t4];
                a[mt][1] = As[r + g + 8][kk + t4];
                a[mt][2] = As[r + g][kk + t4 + 4];
                a[mt][3] = As[r + g + 8][kk + t4 + 4];
            }
#pragma unroll
            for (int nt = 0; nt < 4; nt++) {
                const int n = wn * 32 + nt * 8 + g;
                bf[nt][0] = Bs[n][kk + t4];
                bf[nt][1] = Bs[n][kk + t4 + 4];
            }
#pragma unroll
            for (int mt = 0; mt < 4; mt++)
#pragma unroll
                for (int nt = 0; nt < 4; nt++)
                    mma8(acc[mt][nt], a[mt], bf[nt]);
        }
        __syncthreads();
    }

    // Epilogue: add bias, scatter to [b][h][s][d]
#pragma unroll
    for (int mt = 0; mt < 4; mt++) {
        const int r0 = bm + wm * 64 + mt * 16 + g;
#pragma unroll
        for (int nt = 0; nt < 4; nt++) {
            const int n0  = bn + wn * 32 + nt * 8 + t4 * 2;
            const float b0v = bias[n0];
            const float b1v = bias[n0 + 1];
            const int h = n0 >> 6;
            const int d = n0 & 63;
#pragma unroll
            for (int half = 0; half < 2; half++) {
                const int m  = r0 + half * 8;
                const int s  = m >> 3;     // m = s*B + b
                const int bb = m & 7;
                float2 val = make_float2(acc[mt][nt][half * 2 + 0] + b0v,
                                         acc[mt][nt][half * 2 + 1] + b1v);
                *reinterpret_cast<float2*>(
                    &Out[(((size_t)bb * NHD + h) * SQ + s) * HDI + d]) = val;
            }
        }
    }
}

// ---------------------------------------------------------------------------
// Kernel A: exp-scores.  Block = 128q x 128k for one (b,h).  256 thr, 8 warps
// (2 x 4), warp tile 64x32.  K=64 single pass.  Writes unnormalized exp scores
// to attn and deterministic partial row sums to g_psum[bh][q][kblk].
// __launch_bounds__(256,3): cap regs at 85 -> 3 blocks/SM.
// ---------------------------------------------------------------------------
#define A_SMEM_FLOATS (128 * 68 * 2 + 128 + 128 * 4)
#define A_SMEM_BYTES  (A_SMEM_FLOATS * 4)

__global__ __launch_bounds__(256, 3) void k_scores(float* __restrict__ attn)
{
    extern __shared__ float sm[];
    unsigned* Qs    = (unsigned*)sm;
    unsigned* Ks    = Qs + 128 * 68;
    float*    sBias = (float*)(Ks + 128 * 68);
    float*    sSum  = sBias + 128;

    const int tid  = threadIdx.x;
    const int lane = tid & 31;
    const int warp = tid >> 5;
    const int g    = lane >> 2;
    const int t4   = lane & 3;
    const int kb   = blockIdx.x;
    const int qb   = blockIdx.y;
    const int bh   = blockIdx.z;
    const int b    = bh >> 4;

    const float* Qg = g_qp + ((size_t)bh * SQ + qb * 128) * HDI;
    const float* Kg = g_kp + ((size_t)bh * SQ + kb * 128) * HDI;

#pragma unroll
    for (int t = 0; t < 8; t++) {
        int i4 = tid + t * 256;
        int r  = i4 >> 4;
        int c  = (i4 & 15) << 2;
        float4 q4 = *reinterpret_cast<const float4*>(&Qg[r * 64 + c]);
        *reinterpret_cast<uint4*>(&Qs[r * 68 + c]) = f2tf4(q4);
        float4 k4 = *reinterpret_cast<const float4*>(&Kg[r * 64 + c]);
        *reinterpret_cast<uint4*>(&Ks[r * 68 + c]) = f2tf4(k4);
    }
    if (tid < 128) sBias[tid] = g_bias[b * SQ + kb * 128 + tid];
    __syncthreads();

    const int wm = warp >> 2;   // 0..1
    const int wn = warp & 3;    // 0..3

    float acc[4][4][4];
#pragma unroll
    for (int mt = 0; mt < 4; mt++)
#pragma unroll
        for (int nt = 0; nt < 4; nt++)
#pragma unroll
            for (int i = 0; i < 4; i++) acc[mt][nt][i] = 0.0f;

#pragma unroll
    for (int k8 = 0; k8 < 8; k8++) {
        const int kk = k8 * 8;
        unsigned a[4][4], bf[4][2];
#pragma unroll
        for (int mt = 0; mt < 4; mt++) {
            const int r = wm * 64 + mt * 16;
            a[mt][0] = Qs[(r + g) * 68 + kk + t4];
            a[mt][1] = Qs[(r + g + 8) * 68 + kk + t4];
            a[mt][2] = Qs[(r + g) * 68 + kk + t4 + 4];
            a[mt][3] = Qs[(r + g + 8) * 68 + kk + t4 + 4];
        }
#pragma unroll
        for (int nt = 0; nt < 4; nt++) {
            const int n = wn * 32 + nt * 8 + g;
            bf[nt][0] = Ks[n * 68 + kk + t4];
            bf[nt][1] = Ks[n * 68 + kk + t4 + 4];
        }
#pragma unroll
        for (int mt = 0; mt < 4; mt++)
#pragma unroll
            for (int nt = 0; nt < 4; nt++)
                mma8(acc[mt][nt], a[mt], bf[nt]);
    }

    float* attn_base = attn + ((size_t)bh * SQ + qb * 128) * SQ + kb * 128;
#pragma unroll
    for (int mt = 0; mt < 4; mt++) {
#pragma unroll
        for (int half = 0; half < 2; half++) {
            const int rl = wm * 64 + mt * 16 + g + half * 8;
            float rs = 0.0f;
#pragma unroll
            for (int nt = 0; nt < 4; nt++) {
                const int cl = wn * 32 + nt * 8 + t4 * 2;
                float p0 = __expf(acc[mt][nt][half * 2 + 0] * 0.125f + sBias[cl]);
                float p1 = __expf(acc[mt][nt][half * 2 + 1] * 0.125f + sBias[cl + 1]);
                *reinterpret_cast<float2*>(&attn_base[(size_t)rl * SQ + cl]) =
                    make_float2(p0, p1);
                rs += p0 + p1;
            }
            rs += __shfl_xor_sync(0xffffffffu, rs, 1);
            rs += __shfl_xor_sync(0xffffffffu, rs, 2);
            if (t4 == 0) sSum[rl * 4 + wn] = rs;
        }
    }
    __syncthreads();
    if (tid < 128) {
        float s = sSum[tid * 4] + sSum[tid * 4 + 1] + sSum[tid * 4 + 2] + sSum[tid * 4 + 3];
        g_psum[((size_t)bh * SQ + qb * 128 + tid) * 8 + kb] = s;
    }
}

// ---------------------------------------------------------------------------
// Reduce partial sums -> 1/rowsum (deterministic, no atomics)
// ---------------------------------------------------------------------------
__global__ void k_rsum() {
    int i = blockIdx.x * blockDim.x + threadIdx.x;
    if (i >= BB * NHD * SQ) return;
    const float* p = &g_psum[(size_t)i * 8];
    float s = ((p[0] + p[1]) + (p[2] + p[3])) + ((p[4] + p[5]) + (p[6] + p[7]));
    g_rinv[i] = 1.0f / s;
}

// ---------------------------------------------------------------------------
// Kernel B: ctx = (Pexp @ V) * rinv.  Reads UNNORMALIZED attn (no writeback).
// Block = 128q x 64d for one (b,h); loops over 16 key tiles of 64.
// 256 thr, 8 warps (4 x 2), warp tile 32x32.  smem ~53KB -> 3+ blocks/SM.
// ---------------------------------------------------------------------------
#define B_PS  (128 * 68)
#define B_VS  (64 * 72)
#define B_SMEM_FLOATS (B_PS + B_VS + 128)
#define B_SMEM_BYTES  (B_SMEM_FLOATS * 4)

__global__ __launch_bounds__(256, 3) void k_pv(const float* __restrict__ attn,
                                               float* __restrict__ ctx)
{
    extern __shared__ float sm[];
    unsigned* Ps   = (unsigned*)sm;
    unsigned* Vs   = Ps + B_PS;
    float*    sInv = (float*)(Vs + B_VS);

    const int tid  = threadIdx.x;
    const int lane = tid & 31;
    const int warp = tid >> 5;
    const int g    = lane >> 2;
    const int t4   = lane & 3;
    const int qb   = blockIdx.x;
    const int bh   = blockIdx.y;
    const int b    = bh >> 4;
    const int h    = bh & 15;

    if (tid < 128) sInv[tid] = g_rinv[(size_t)bh * SQ + qb * 128 + tid];

    const float* attn_base = attn + ((size_t)bh * SQ + qb * 128) * SQ;
    const float* Vg        = g_vp + (size_t)bh * SQ * HDI;

    const int wm = warp >> 1;   // 0..3
    const int wn = warp & 1;    // 0..1

    float o[2][4][4];
#pragma unroll
    for (int mt = 0; mt < 2; mt++)
#pragma unroll
        for (int nt = 0; nt < 4; nt++)
#pragma unroll
            for (int i = 0; i < 4; i++) o[mt][nt][i] = 0.0f;

    for (int kt = 0; kt < 16; kt++) {
        __syncthreads();   // protects Ps/Vs reuse (and sInv on kt=0)
        // P tile 128x64: pure load -> tf32 stage (no scaling, no writeback)
#pragma unroll
        for (int t = 0; t < 8; t++) {
            int i4 = tid + t * 256;
            int r  = i4 >> 4;
            int c  = (i4 & 15) << 2;
            float4 p = *reinterpret_cast<const float4*>(
                &attn_base[(size_t)r * SQ + kt * 64 + c]);
            *reinterpret_cast<uint4*>(&Ps[r * 68 + c]) = f2tf4(p);
        }
        // V tile 64x64
#pragma unroll
        for (int t = 0; t < 4; t++) {
            int i4 = tid + t * 256;
            int r  = i4 >> 4;
            int c  = (i4 & 15) << 2;
            float4 v = *reinterpret_cast<const float4*>(&Vg[(size_t)(kt * 64 + r) * 64 + c]);
            *reinterpret_cast<uint4*>(&Vs[r * 72 + c]) = f2tf4(v);
        }
        __syncthreads();

#pragma unroll
        for (int k8 = 0; k8 < 8; k8++) {
            const int kk = k8 * 8;
            unsigned a[2][4], bf[4][2];
#pragma unroll
            for (int mt = 0; mt < 2; mt++) {
                const int r = wm * 32 + mt * 16;
                a[mt][0] = Ps[(r + g) * 68 + kk + t4];
                a[mt][1] = Ps[(r + g + 8) * 68 + kk + t4];
                a[mt][2] = Ps[(r + g) * 68 + kk + t4 + 4];
                a[mt][3] = Ps[(r + g + 8) * 68 + kk + t4 + 4];
            }
#pragma unroll
            for (int nt = 0; nt < 4; nt++) {
                const int n = wn * 32 + nt * 8 + g;   // head-dim column
                bf[nt][0] = Vs[(kk + t4) * 72 + n];
                bf[nt][1] = Vs[(kk + t4 + 4) * 72 + n];
            }
#pragma unroll
            for (int mt = 0; mt < 2; mt++)
#pragma unroll
                for (int nt = 0; nt < 4; nt++)
                    mma8(o[mt][nt], a[mt], bf[nt]);
        }
    }

    // Epilogue: ctx[s][b][h*64+d] = o * rinv[row]
#pragma unroll
    for (int mt = 0; mt < 2; mt++)
#pragma unroll
        for (int nt = 0; nt < 4; nt++)
#pragma unroll
            for (int half = 0; half < 2; half++) {
                int row = wm * 32 + mt * 16 + g + half * 8;
                int s   = qb * 128 + row;
                int d   = wn * 32 + nt * 8 + t4 * 2;
                float inv = sInv[row];
                float2 val = make_float2(o[mt][nt][half * 2 + 0] * inv,
                                         o[mt][nt][half * 2 + 1] * inv);
                *reinterpret_cast<float2*>(
                    &ctx[((size_t)s * BB + b) * HH + h * HDI + d]) = val;
            }
}

// ---------------------------------------------------------------------------
// Kernel C: streaming normalize  attn[row][*] *= rinv[row].
// Each 256-thread block iteration covers exactly one 1024-float row
// (256 float4), so rinv is a broadcast load.  Pure bandwidth.
// ---------------------------------------------------------------------------
__global__ __launch_bounds__(256) void k_norm(float* __restrict__ attn)
{
    const size_t n4 = (size_t)BB * NHD * SQ * SQ / 4;   // 33.5M float4
    float4* a4 = reinterpret_cast<float4*>(attn);
    for (size_t i = (size_t)blockIdx.x * blockDim.x + threadIdx.x;
         i < n4; i += (size_t)gridDim.x * blockDim.x) {
        const size_t row = i >> 8;          // 256 float4 per row
        const float inv = g_rinv[row];
        float4 p = a4[i];
        p.x *= inv; p.y *= inv; p.z *= inv; p.w *= inv;
        a4[i] = p;
    }
}

// ---------------------------------------------------------------------------
// Launch
// ---------------------------------------------------------------------------
extern "C" void kernel_launch(void* const* d_in, const int* in_sizes, int n_in,
                              void* d_out, int out_size)
{
    const float* q    = (const float*)d_in[0];
    const float* k    = (const float*)d_in[1];
    const float* v    = (const float*)d_in[2];
    const void*  mask = d_in[3];
    const float* Wq   = (const float*)d_in[4];
    const float* bq   = (const float*)d_in[5];
    const float* Wk   = (const float*)d_in[6];
    const float* bk   = (const float*)d_in[7];
    const float* Wv   = (const float*)d_in[8];
    const float* bv   = (const float*)d_in[9];

    float* out  = (float*)d_out;
    float* ctx  = out;                               // [S,B,H]
    float* attn = out + (size_t)SQ * BB * HH;        // [B,NH,S,S]

    k_detect<<<1, 1>>>((const unsigned*)mask);
    k_bias<<<(BB * SQ + 255) / 256, 256>>>(mask);

    k_proj<<<dim3(HH / 128, (BB * SQ) / 128, 3), 256>>>(
        q, k, v, Wq, bq, Wk, bk, Wv, bv);

    cudaFuncSetAttribute(k_scores, cudaFuncAttributeMaxDynamicSharedMemorySize,
                         A_SMEM_BYTES);
    k_scores<<<dim3(SQ / 128, SQ / 128, BB * NHD), 256, A_SMEM_BYTES>>>(attn);

    k_rsum<<<(BB * NHD * SQ + 255) / 256, 256>>>();

    cudaFuncSetAttribute(k_pv, cudaFuncAttributeMaxDynamicSharedMemorySize,
                         B_SMEM_BYTES);
    k_pv<<<dim3(SQ / 128, BB * NHD), 256, B_SMEM_BYTES>>>(attn, ctx);

    k_norm<<<148 * 16, 256>>>(attn);
}

// round 10
// speedup vs baseline: 1.5744x; 1.5744x over previous
#include <cuda_runtime.h>
#include <cuda_bf16.h>

// Problem constants
#define SQ   1024   // sequence length
#define BB   8      // batch
#define HH   1024   // hidden
#define NHD  16     // num heads
#define HDI  64     // head dim

// ---------------------------------------------------------------------------
// Scratch (device globals: no allocation allowed)
// ---------------------------------------------------------------------------
__device__ float g_qp[(size_t)BB * NHD * SQ * HDI];   // [b][h][s][d]
__device__ float g_kp[(size_t)BB * NHD * SQ * HDI];
__device__ float g_vp[(size_t)BB * NHD * SQ * HDI];
__device__ float g_bias[BB * SQ];                     // -1e6 * mask
__device__ int   g_mmode;

// ---------------------------------------------------------------------------
// TF32 helpers
// ---------------------------------------------------------------------------
__device__ __forceinline__ unsigned f2tf(float x) {
    unsigned u;
    asm("cvt.rna.tf32.f32 %0, %1;" : "=r"(u) : "f"(x));
    return u;
}
__device__ __forceinline__ uint4 f2tf4(float4 v) {
    return make_uint4(f2tf(v.x), f2tf(v.y), f2tf(v.z), f2tf(v.w));
}
__device__ __forceinline__ void mma8(float c[4], const unsigned a[4], const unsigned b[2]) {
    asm volatile(
        "mma.sync.aligned.m16n8k8.row.col.f32.tf32.tf32.f32 "
        "{%0,%1,%2,%3}, {%4,%5,%6,%7}, {%8,%9}, {%0,%1,%2,%3};"
        : "+f"(c[0]), "+f"(c[1]), "+f"(c[2]), "+f"(c[3])
        : "r"(a[0]), "r"(a[1]), "r"(a[2]), "r"(a[3]),
          "r"(b[0]), "r"(b[1]));
}

// ---------------------------------------------------------------------------
// Mask dtype detection + bias build
// ---------------------------------------------------------------------------
__global__ void k_detect(const unsigned* __restrict__ m) {
    bool i32 = true, f32 = true;
    for (int i = 0; i < 2048; i++) {
        unsigned v = m[i];
        if (v > 1u) i32 = false;
        if (v != 0u && v != 0x3F800000u) f32 = false;
    }
    g_mmode = i32 ? 1 : (f32 ? 2 : 0);
}
__global__ void k_bias(const void* __restrict__ mask) {
    int i = blockIdx.x * blockDim.x + threadIdx.x;
    if (i >= BB * SQ) return;
    int mode = g_mmode;
    float v;
    if (mode == 1)      v = (float)((const int*)mask)[i];
    else if (mode == 2) v = ((const float*)mask)[i];
    else                v = (float)((const unsigned char*)mask)[i];
    g_bias[i] = v * -1000000.0f;
}

// ---------------------------------------------------------------------------
// Projection GEMM (unchanged known-good R5 version, all 3 in one launch):
//   Out[b][h][s][d] = X[m=s*B+b] . W[n] + bias[n]
// BM=128, BN=128, BK=32, 256 thr = 8 warps (2 x 4), warp tile 64x32.
// ---------------------------------------------------------------------------
__global__ __launch_bounds__(256) void k_proj(
    const float* __restrict__ Xq, const float* __restrict__ Xk, const float* __restrict__ Xv,
    const float* __restrict__ Wq, const float* __restrict__ bq,
    const float* __restrict__ Wk, const float* __restrict__ bk,
    const float* __restrict__ Wv, const float* __restrict__ bv)
{
    const int which = blockIdx.z;
    const float* X    = (which == 0) ? Xq : ((which == 1) ? Xk : Xv);
    const float* W    = (which == 0) ? Wq : ((which == 1) ? Wk : Wv);
    const float* bias = (which == 0) ? bq : ((which == 1) ? bk : bv);
    float* Out        = (which == 0) ? g_qp : ((which == 1) ? g_kp : g_vp);

    __shared__ unsigned As[128][36];
    __shared__ unsigned Bs[128][36];

    const int tid  = threadIdx.x;
    const int lane = tid & 31;
    const int warp = tid >> 5;
    const int wm   = warp >> 2;     // 0..1
    const int wn   = warp & 3;      // 0..3
    const int g    = lane >> 2;
    const int t4   = lane & 3;
    const int bm   = blockIdx.y * 128;
    const int bn   = blockIdx.x * 128;

    float acc[4][4][4];
#pragma unroll
    for (int mt = 0; mt < 4; mt++)
#pragma unroll
        for (int nt = 0; nt < 4; nt++)
#pragma unroll
            for (int i = 0; i < 4; i++) acc[mt][nt][i] = 0.0f;

    for (int k0 = 0; k0 < HH; k0 += 32) {
#pragma unroll
        for (int t = 0; t < 4; t++) {
            int i4 = tid + t * 256;
            int r  = i4 >> 3;
            int c  = (i4 & 7) << 2;
            float4 a4 = *reinterpret_cast<const float4*>(&X[(size_t)(bm + r) * HH + k0 + c]);
            *reinterpret_cast<uint4*>(&As[r][c]) = f2tf4(a4);
            float4 b4 = *reinterpret_cast<const float4*>(&W[(size_t)(bn + r) * HH + k0 + c]);
            *reinterpret_cast<uint4*>(&Bs[r][c]) = f2tf4(b4);
        }
        __syncthreads();

#pragma unroll
        for (int k8 = 0; k8 < 4; k8++) {
            const int kk = k8 * 8;
            unsigned a[4][4], bf[4][2];
#pragma unroll
            for (int mt = 0; mt < 4; mt++) {
                const int r = wm * 64 + mt * 16;
                a[mt][0] = As[r + g][kk + t4];
                a[mt][1] = As[r + g + 8][kk + t4];
                a[mt][2] = As[r + g][kk + t4 + 4];
                a[mt][3] = As[r + g + 8][kk + t4 + 4];
            }
#pragma unroll
            for (int nt = 0; nt < 4; nt++) {
                const int n = wn * 32 + nt * 8 + g;
                bf[nt][0] = Bs[n][kk + t4];
                bf[nt][1] = Bs[n][kk + t4 + 4];
            }
#pragma unroll
            for (int mt = 0; mt < 4; mt++)
#pragma unroll
                for (int nt = 0; nt < 4; nt++)
                    mma8(acc[mt][nt], a[mt], bf[nt]);
        }
        __syncthreads();
    }

#pragma unroll
    for (int mt = 0; mt < 4; mt++) {
        const int r0 = bm + wm * 64 + mt * 16 + g;
#pragma unroll
        for (int nt = 0; nt < 4; nt++) {
            const int n0  = bn + wn * 32 + nt * 8 + t4 * 2;
            const float b0v = bias[n0];
            const float b1v = bias[n0 + 1];
            const int h = n0 >> 6;
            const int d = n0 & 63;
#pragma unroll
            for (int half = 0; half < 2; half++) {
                const int m  = r0 + half * 8;
                const int s  = m >> 3;     // m = s*B + b
                const int bb = m & 7;
                float2 val = make_float2(acc[mt][nt][half * 2 + 0] + b0v,
                                         acc[mt][nt][half * 2 + 1] + b1v);
                *reinterpret_cast<float2*>(
                    &Out[(((size_t)bb * NHD + h) * SQ + s) * HDI + d]) = val;
            }
        }
    }
}

// ---------------------------------------------------------------------------
// Fused two-pass flash attention.  One block = 128 q-rows of one (b,h).
// 256 thr = 8 warps: wm = warp>>1 (0..3, 32 q-rows), wn = warp&1 (0..1, 32 cols).
// Pass 1: loop 16 k-tiles (64 keys), S = Q.K^T, accumulate exp row sums in regs.
// Pass 2: recompute S, write NORMALIZED attn once, stage P (tf32), O += P.V.
// attn tensor touched exactly once.  smem ~111KB -> 2 blocks/SM.
// ---------------------------------------------------------------------------
#define F_QS   (128 * 68)
#define F_KS   (64 * 68)
#define F_VS   (64 * 72)
#define F_PS   (128 * 68)
#define F_BIAS 1024
#define F_SMEM_FLOATS (F_QS + F_KS + F_VS + F_PS + F_BIAS + 256 + 128)
#define F_SMEM_BYTES  (F_SMEM_FLOATS * 4)

__global__ __launch_bounds__(256, 2) void k_attn(float* __restrict__ attn,
                                                 float* __restrict__ ctx)
{
    extern __shared__ float sm[];
    unsigned* Qs    = (unsigned*)sm;
    unsigned* Ks    = Qs + F_QS;
    unsigned* Vs    = Ks + F_KS;
    unsigned* Ps    = Vs + F_VS;
    float*    sBias = (float*)(Ps + F_PS);
    float*    sSum  = sBias + F_BIAS;
    float*    sInv  = sSum + 256;

    const int tid  = threadIdx.x;
    const int lane = tid & 31;
    const int warp = tid >> 5;
    const int g    = lane >> 2;
    const int t4   = lane & 3;
    const int wm   = warp >> 1;    // 0..3
    const int wn   = warp & 1;     // 0..1
    const int qb   = blockIdx.x;
    const int bh   = blockIdx.y;
    const int b    = bh >> 4;
    const int h    = bh & 15;

    const float* Qg = g_qp + ((size_t)bh * SQ + qb * 128) * HDI;
    const float* Kg = g_kp + (size_t)bh * SQ * HDI;
    const float* Vg = g_vp + (size_t)bh * SQ * HDI;

    // Load Q tile (128x64, tf32) and bias row (1024)
#pragma unroll
    for (int t = 0; t < 8; t++) {
        int i4 = tid + t * 256;
        int r  = i4 >> 4;
        int c  = (i4 & 15) << 2;
        float4 q4 = *reinterpret_cast<const float4*>(&Qg[r * 64 + c]);
        *reinterpret_cast<uint4*>(&Qs[r * 68 + c]) = f2tf4(q4);
    }
#pragma unroll
    for (int t = 0; t < 4; t++) sBias[tid + t * 256] = g_bias[b * SQ + tid + t * 256];

    // ======================= Pass 1: row sums ============================
    float rs[2][2] = {};
    for (int kt = 0; kt < 16; kt++) {
        __syncthreads();   // protect Ks reuse (and Qs/bias load on kt=0)
#pragma unroll
        for (int t = 0; t < 4; t++) {
            int i4 = tid + t * 256;
            int r  = i4 >> 4;
            int c  = (i4 & 15) << 2;
            float4 k4 = *reinterpret_cast<const float4*>(&Kg[(size_t)(kt * 64 + r) * 64 + c]);
            *reinterpret_cast<uint4*>(&Ks[r * 68 + c]) = f2tf4(k4);
        }
        __syncthreads();

        float acc[2][4][4] = {};
#pragma unroll
        for (int k8 = 0; k8 < 8; k8++) {
            const int kk = k8 * 8;
            unsigned a[2][4], bf[4][2];
#pragma unroll
            for (int mt = 0; mt < 2; mt++) {
                const int r = wm * 32 + mt * 16;
                a[mt][0] = Qs[(r + g) * 68 + kk + t4];
                a[mt][1] = Qs[(r + g + 8) * 68 + kk + t4];
                a[mt][2] = Qs[(r + g) * 68 + kk + t4 + 4];
                a[mt][3] = Qs[(r + g + 8) * 68 + kk + t4 + 4];
            }
#pragma unroll
            for (int nt = 0; nt < 4; nt++) {
                const int n = wn * 32 + nt * 8 + g;
                bf[nt][0] = Ks[n * 68 + kk + t4];
                bf[nt][1] = Ks[n * 68 + kk + t4 + 4];
            }
#pragma unroll
            for (int mt = 0; mt < 2; mt++)
#pragma unroll
                for (int nt = 0; nt < 4; nt++)
                    mma8(acc[mt][nt], a[mt], bf[nt]);
        }
#pragma unroll
        for (int mt = 0; mt < 2; mt++)
#pragma unroll
            for (int half = 0; half < 2; half++)
#pragma unroll
                for (int nt = 0; nt < 4; nt++) {
                    const int cl = kt * 64 + wn * 32 + nt * 8 + t4 * 2;
                    rs[mt][half] += __expf(acc[mt][nt][half * 2 + 0] * 0.125f + sBias[cl])
                                  + __expf(acc[mt][nt][half * 2 + 1] * 0.125f + sBias[cl + 1]);
                }
    }
    // reduce over t4 lanes, combine both wn warps via smem
#pragma unroll
    for (int mt = 0; mt < 2; mt++)
#pragma unroll
        for (int half = 0; half < 2; half++) {
            float v = rs[mt][half];
            v += __shfl_xor_sync(0xffffffffu, v, 1);
            v += __shfl_xor_sync(0xffffffffu, v, 2);
            if (t4 == 0) {
                const int row = wm * 32 + mt * 16 + g + half * 8;
                sSum[row * 2 + wn] = v;
            }
        }
    __syncthreads();
    if (tid < 128) sInv[tid] = 1.0f / (sSum[tid * 2] + sSum[tid * 2 + 1]);

    // ======================= Pass 2: attn + O ============================
    float o[2][4][4] = {};
    float* attn_base = attn + ((size_t)bh * SQ + qb * 128) * SQ;

    for (int kt = 0; kt < 16; kt++) {
        __syncthreads();   // prev PV reads done; sInv visible on kt=0
#pragma unroll
        for (int t = 0; t < 4; t++) {
            int i4 = tid + t * 256;
            int r  = i4 >> 4;
            int c  = (i4 & 15) << 2;
            float4 k4 = *reinterpret_cast<const float4*>(&Kg[(size_t)(kt * 64 + r) * 64 + c]);
            *reinterpret_cast<uint4*>(&Ks[r * 68 + c]) = f2tf4(k4);
            float4 v4 = *reinterpret_cast<const float4*>(&Vg[(size_t)(kt * 64 + r) * 64 + c]);
            *reinterpret_cast<uint4*>(&Vs[r * 72 + c]) = f2tf4(v4);
        }
        __syncthreads();

        float acc[2][4][4] = {};
#pragma unroll
        for (int k8 = 0; k8 < 8; k8++) {
            const int kk = k8 * 8;
            unsigned a[2][4], bf[4][2];
#pragma unroll
            for (int mt = 0; mt < 2; mt++) {
                const int r = wm * 32 + mt * 16;
                a[mt][0] = Qs[(r + g) * 68 + kk + t4];
                a[mt][1] = Qs[(r + g + 8) * 68 + kk + t4];
                a[mt][2] = Qs[(r + g) * 68 + kk + t4 + 4];
                a[mt][3] = Qs[(r + g + 8) * 68 + kk + t4 + 4];
            }
#pragma unroll
            for (int nt = 0; nt < 4; nt++) {
                const int n = wn * 32 + nt * 8 + g;
                bf[nt][0] = Ks[n * 68 + kk + t4];
                bf[nt][1] = Ks[n * 68 + kk + t4 + 4];
            }
#pragma unroll
            for (int mt = 0; mt < 2; mt++)
#pragma unroll
                for (int nt = 0; nt < 4; nt++)
                    mma8(acc[mt][nt], a[mt], bf[nt]);
        }

        // normalized exp -> attn (single write) + Ps (tf32 stage)
#pragma unroll
        for (int mt = 0; mt < 2; mt++)
#pragma unroll
            for (int half = 0; half < 2; half++) {
                const int row = wm * 32 + mt * 16 + g + half * 8;
                const float inv = sInv[row];
#pragma unroll
                for (int nt = 0; nt < 4; nt++) {
                    const int cl = wn * 32 + nt * 8 + t4 * 2;
                    const int key = kt * 64 + cl;
                    float p0 = __expf(acc[mt][nt][half * 2 + 0] * 0.125f + sBias[key]) * inv;
                    float p1 = __expf(acc[mt][nt][half * 2 + 1] * 0.125f + sBias[key + 1]) * inv;
                    *reinterpret_cast<float2*>(&attn_base[(size_t)row * SQ + key]) =
                        make_float2(p0, p1);
                    Ps[row * 68 + cl]     = f2tf(p0);
                    Ps[row * 68 + cl + 1] = f2tf(p1);
                }
            }
        __syncthreads();   // Ps complete

        // O += P . V
#pragma unroll
        for (int k8 = 0; k8 < 8; k8++) {
            const int kk = k8 * 8;
            unsigned a[2][4], bf[4][2];
#pragma unroll
            for (int mt = 0; mt < 2; mt++) {
                const int r = wm * 32 + mt * 16;
                a[mt][0] = Ps[(r + g) * 68 + kk + t4];
                a[mt][1] = Ps[(r + g + 8) * 68 + kk + t4];
                a[mt][2] = Ps[(r + g) * 68 + kk + t4 + 4];
                a[mt][3] = Ps[(r + g + 8) * 68 + kk + t4 + 4];
            }
#pragma unroll
            for (int nt = 0; nt < 4; nt++) {
                const int n = wn * 32 + nt * 8 + g;   // head-dim column
                bf[nt][0] = Vs[(kk + t4) * 72 + n];
                bf[nt][1] = Vs[(kk + t4 + 4) * 72 + n];
            }
#pragma unroll
            for (int mt = 0; mt < 2; mt++)
#pragma unroll
                for (int nt = 0; nt < 4; nt++)
                    mma8(o[mt][nt], a[mt], bf[nt]);
        }
    }

    // Epilogue: ctx[s][b][h*64+d]  (already normalized)
#pragma unroll
    for (int mt = 0; mt < 2; mt++)
#pragma unroll
        for (int nt = 0; nt < 4; nt++)
#pragma unroll
            for (int half = 0; half < 2; half++) {
                int row = wm * 32 + mt * 16 + g + half * 8;
                int s   = qb * 128 + row;
                int d   = wn * 32 + nt * 8 + t4 * 2;
                float2 val = make_float2(o[mt][nt][half * 2 + 0],
                                         o[mt][nt][half * 2 + 1]);
                *reinterpret_cast<float2*>(
                    &ctx[((size_t)s * BB + b) * HH + h * HDI + d]) = val;
            }
}

// ---------------------------------------------------------------------------
// Launch
// ---------------------------------------------------------------------------
extern "C" void kernel_launch(void* const* d_in, const int* in_sizes, int n_in,
                              void* d_out, int out_size)
{
    const float* q    = (const float*)d_in[0];
    const float* k    = (const float*)d_in[1];
    const float* v    = (const float*)d_in[2];
    const void*  mask = d_in[3];
    const float* Wq   = (const float*)d_in[4];
    const float* bq   = (const float*)d_in[5];
    const float* Wk   = (const float*)d_in[6];
    const float* bk   = (const float*)d_in[7];
    const float* Wv   = (const float*)d_in[8];
    const float* bv   = (const float*)d_in[9];

    float* out  = (float*)d_out;
    float* ctx  = out;                               // [S,B,H]
    float* attn = out + (size_t)SQ * BB * HH;        // [B,NH,S,S]

    k_detect<<<1, 1>>>((const unsigned*)mask);
    k_bias<<<(BB * SQ + 255) / 256, 256>>>(mask);

    k_proj<<<dim3(HH / 128, (BB * SQ) / 128, 3), 256>>>(
        q, k, v, Wq, bq, Wk, bk, Wv, bv);

    cudaFuncSetAttribute(k_attn, cudaFuncAttributeMaxDynamicSharedMemorySize,
                         F_SMEM_BYTES);
    k_attn<<<dim3(SQ / 128, BB * NHD), 256, F_SMEM_BYTES>>>(attn, ctx);
}